// round 8
// baseline (speedup 1.0000x reference)
#include <cuda_runtime.h>
#include <cuda_fp16.h>
#include <cstdint>

#define SEQ 2048
#define DM 1024
#define NH 16
#define HD 64
#define BT 4
#define MTOT (BT*SEQ)          // 8192
#define WSZ (DM*DM)

// gemm smem: 3 stages x 2 arrays (A,B) x 128 rows x 64 halfs (stride 72)
#define GSTR 72
#define GARR (128*GSTR)         // 9216 halfs per array
#define GSTAGE (2*GARR)         // 18432 halfs per stage
#define GNSTG 3
#define GSMEM_BYTES (GNSTG*GSTAGE*2)   // 110592 bytes

// attn smem: 2 stages x 2 arrays (K,V) x 128 rows x 64 halfs (stride 72)
#define ASTR 72
#define AARR (128*ASTR)         // 9216 halfs per array
#define ASTAGE (2*AARR)         // 18432 halfs per stage
#define ASMEM_BYTES (2*ASTAGE*2)   // 73728 bytes

// -------- scratch (static device globals; allocation-free) --------
__device__ __align__(16) __half g_xh[MTOT*DM];
__device__ __align__(16) __half g_wth[4*WSZ];
__device__ __align__(16) __half g_qh[MTOT*DM];
__device__ __align__(16) __half g_kh[MTOT*DM];
__device__ __align__(16) __half g_vh[MTOT*DM];
__device__ __align__(16) __half g_aoh[MTOT*DM];
__device__ float g_ropec[SEQ*32];
__device__ float g_ropes[SEQ*32];

__device__ __forceinline__ void cpasync16(__half* s, const __half* g){
  uint32_t sa = (uint32_t)__cvta_generic_to_shared(s);
  asm volatile("cp.async.cg.shared.global [%0], [%1], 16;\n" :: "r"(sa), "l"(g));
}
__device__ __forceinline__ void ldmx4(uint32_t& r0, uint32_t& r1, uint32_t& r2, uint32_t& r3,
                                      const __half* p){
  uint32_t a = (uint32_t)__cvta_generic_to_shared(p);
  asm volatile("ldmatrix.sync.aligned.m8n8.x4.shared.b16 {%0,%1,%2,%3}, [%4];\n"
    : "=r"(r0), "=r"(r1), "=r"(r2), "=r"(r3) : "r"(a));
}
__device__ __forceinline__ void ldmx4t(uint32_t& r0, uint32_t& r1, uint32_t& r2, uint32_t& r3,
                                       const __half* p){
  uint32_t a = (uint32_t)__cvta_generic_to_shared(p);
  asm volatile("ldmatrix.sync.aligned.m8n8.x4.trans.shared.b16 {%0,%1,%2,%3}, [%4];\n"
    : "=r"(r0), "=r"(r1), "=r"(r2), "=r"(r3) : "r"(a));
}
__device__ __forceinline__ void mma16816(float* c, const uint32_t* a, uint32_t b0, uint32_t b1){
  asm volatile(
    "mma.sync.aligned.m16n8k16.row.col.f32.f16.f16.f32 "
    "{%0,%1,%2,%3}, {%4,%5,%6,%7}, {%8,%9}, {%0,%1,%2,%3};\n"
    : "+f"(c[0]), "+f"(c[1]), "+f"(c[2]), "+f"(c[3])
    : "r"(a[0]), "r"(a[1]), "r"(a[2]), "r"(a[3]), "r"(b0), "r"(b1));
}

// -------- conversion / table kernels --------
__global__ void conv_x_kernel(const float* __restrict__ x){
  int i = (blockIdx.x*blockDim.x + threadIdx.x)*4;
  float4 f = *reinterpret_cast<const float4*>(x + i);
  *reinterpret_cast<__half2*>(g_xh+i)   = __floats2half2_rn(f.x, f.y);
  *reinterpret_cast<__half2*>(g_xh+i+2) = __floats2half2_rn(f.z, f.w);
}

// rope table: cos/sin(pos * 10000^(-2j/64)) for pos in [0,2048), j in [0,32)
__global__ void rope_tab_kernel(){
  int i = blockIdx.x*blockDim.x + threadIdx.x;
  int p = i>>5, j = i&31;
  float fr = exp2f(-0.20762050593046013f * (float)(2*j));
  float sn, cs;
  sincosf((float)p*fr, &sn, &cs);
  g_ropec[i] = cs;
  g_ropes[i] = sn;
}

// transpose-convert: wt[n][k] = W[k][n].  blockIdx.z selects weight.
__global__ void conv_wt_kernel(const float* __restrict__ W0, const float* __restrict__ W1,
                               const float* __restrict__ W2, const float* __restrict__ W3){
  __shared__ float s[32][33];
  const int which = blockIdx.z;
  const float* W = (which==0)?W0:(which==1)?W1:(which==2)?W2:W3;
  int n0 = blockIdx.x*32, k0 = blockIdx.y*32;
  int tx = threadIdx.x, ty = threadIdx.y;
  #pragma unroll
  for (int i=0;i<32;i+=8) s[ty+i][tx] = W[(size_t)(k0+ty+i)*DM + n0+tx];
  __syncthreads();
  __half* dh = g_wth + (size_t)which*WSZ;
  #pragma unroll
  for (int i=0;i<32;i+=8)
    dh[(n0+ty+i)*DM + k0+tx] = __float2half_rn(s[tx][ty+i]);
}

// -------- fp16 GEMM, cp.async 3-stage pipeline (k=64 chunks), ldmatrix fragments --------
// mode = mode_base + blockIdx.z: 0/1/2 = q/k/v projection (rope on 0,1), 3 = output projection
__global__ __launch_bounds__(256) void gemm_kernel(int mode_base,
                                                   const float* __restrict__ bias0,
                                                   const float* __restrict__ bias1,
                                                   const float* __restrict__ bias2,
                                                   const int* __restrict__ ropep,
                                                   float* __restrict__ outp){
  extern __shared__ __half ds[];

  const int mode = mode_base + blockIdx.z;
  const float* bias = (blockIdx.z==0)?bias0:(blockIdx.z==1)?bias1:bias2;

  const __half* Ah = (mode==3) ? g_aoh : g_xh;
  const __half* Bh = g_wth + (size_t)mode*WSZ;

  const int m0 = blockIdx.y*128;
  const int n0 = blockIdx.x*128;
  const int tid = threadIdx.x;
  const int warp = tid>>5, lane = tid&31;
  const int wm = warp>>1, wn = warp&1;
  const int gi = lane>>2, qd = lane&3;
  const int lrow = tid>>1, lcolh = (tid&1)*32;   // 2 threads/row, 32 halfs each
  const int lg = lane>>3, lri = lane&7;

  const __half* gA = Ah + (size_t)(m0+lrow)*DM + lcolh;
  const __half* gB = Bh + (size_t)(n0+lrow)*DM + lcolh;

  float acc[2][8][4];
  #pragma unroll
  for (int a=0;a<2;a++)
    #pragma unroll
    for (int b=0;b<8;b++)
      #pragma unroll
      for (int c=0;c<4;c++) acc[a][b][c]=0.f;

  const int soff = lrow*GSTR + lcolh;
  const int NT = DM/64;   // 16

  // prologue: stages 0,1
  #pragma unroll
  for (int p=0;p<2;p++){
    __half* s = ds + p*GSTAGE;
    int kt = p*64;
    #pragma unroll
    for (int u=0;u<4;u++){
      cpasync16(s+soff+u*8,      gA+kt+u*8);
      cpasync16(s+GARR+soff+u*8, gB+kt+u*8);
    }
    asm volatile("cp.async.commit_group;\n");
  }

  int wstg = 2;
  for (int t=0; t<NT; ++t){
    if (t+2 < NT){
      __half* s = ds + wstg*GSTAGE;
      int kt = (t+2)*64;
      #pragma unroll
      for (int u=0;u<4;u++){
        cpasync16(s+soff+u*8,      gA+kt+u*8);
        cpasync16(s+GARR+soff+u*8, gB+kt+u*8);
      }
      if (++wstg == GNSTG) wstg = 0;
    }
    asm volatile("cp.async.commit_group;\n");
    asm volatile("cp.async.wait_group 2;\n");
    __syncthreads();

    const __half* Ash = ds + (t%GNSTG)*GSTAGE;
    const __half* Bsh = Ash + GARR;

    #pragma unroll
    for (int ks=0; ks<64; ks+=16){
      uint32_t afh[2][4];
      const int arow = lane&15;
      const int acol = ks + (lane>>4)*8;
      #pragma unroll
      for (int mi=0;mi<2;mi++){
        int r = wm*32 + mi*16 + arow;
        ldmx4(afh[mi][0],afh[mi][1],afh[mi][2],afh[mi][3], &Ash[r*GSTR + acol]);
      }
      #pragma unroll
      for (int nip=0; nip<8; nip+=2){
        int row = wn*64 + (nip + (lg>>1))*8 + lri;
        int col = ks + (lg&1)*8;
        uint32_t b0,b1,b2,b3;
        ldmx4(b0,b1,b2,b3, &Bsh[row*GSTR + col]);
        #pragma unroll
        for (int mi=0;mi<2;mi++){
          mma16816(acc[mi][nip],   afh[mi], b0, b1);
          mma16816(acc[mi][nip+1], afh[mi], b2, b3);
        }
      }
    }
    __syncthreads();
  }

  const int start = (mode<=1) ? *ropep : 0;
  #pragma unroll
  for (int mi=0;mi<2;mi++){
    #pragma unroll
    for (int ni=0;ni<8;ni++){
      int mrow = m0 + wm*32 + mi*16 + gi;
      int ncol = n0 + wn*64 + ni*8 + qd*2;
      float b0v = bias[ncol], b1v = bias[ncol+1];
      #pragma unroll
      for (int hf=0; hf<2; hf++){
        int mr = mrow + hf*8;
        float v0 = acc[mi][ni][hf*2+0] + b0v;
        float v1 = acc[mi][ni][hf*2+1] + b1v;
        if (mode==3){
          *reinterpret_cast<float2*>(outp + (size_t)mr*DM + ncol) = make_float2(v0,v1);
        } else {
          int bb = mr >> 11, ss = mr & 2047;
          int hh = ncol >> 6, dd = ncol & 63;
          if (mode<=1 && ss >= start){
            int pos = ss - start;
            int j   = (dd>>1);
            float cs = g_ropec[pos*32 + j];
            float sn = g_ropes[pos*32 + j];
            float e = v0*cs - v1*sn;
            float o = v1*cs + v0*sn;
            v0 = e; v1 = o;
          }
          int off = ((bb*NH + hh)*SEQ + ss)*HD + dd;
          __half* dh = (mode==0)?g_qh:(mode==1)?g_kh:g_vh;
          *reinterpret_cast<__half2*>(dh+off) = __floats2half2_rn(v0,v1);
        }
      }
    }
  }
}

// -------- flash attention: 128-query tile, 8 warps, 128-row KV tiles (2 sub-passes),
// cp.async 2-stage pipeline, ldmatrix.x4 / x4.trans fragments --------
__global__ __launch_bounds__(256) void attn_kernel(){
  extern __shared__ __half ds[];

  const int bh = blockIdx.y;
  const int s0 = blockIdx.x*128;
  const int tid = threadIdx.x;
  const int warp = tid>>5, lane = tid&31;
  const int gi = lane>>2, qd = lane&3;

  const __half* qh = g_qh + (size_t)bh*SEQ*HD;
  const __half* kh = g_kh + (size_t)bh*SEQ*HD;
  const __half* vh = g_vh + (size_t)bh*SEQ*HD;

  // ---- stage Q (128 rows x 64) in stage-0 K array, pull fragments ----
  {
    __half* Qh = ds;
    for (int idx=tid; idx<1024; idx+=256){
      int rr = idx>>3, c = (idx&7)*8;
      *reinterpret_cast<uint4*>(&Qh[rr*ASTR+c]) = *reinterpret_cast<const uint4*>(qh + (size_t)(s0+rr)*HD + c);
    }
  }
  __syncthreads();
  uint32_t qfh[4][4];
  {
    const __half* Qh = ds;
    const int arow = lane&15;
    #pragma unroll
    for (int kk=0;kk<4;kk++){
      int r = warp*16 + arow;
      int c = kk*16 + (lane>>4)*8;
      ldmx4(qfh[kk][0],qfh[kk][1],qfh[kk][2],qfh[kk][3], &Qh[r*ASTR + c]);
    }
  }
  __syncthreads();

  float mlo=-1e30f, mhi=-1e30f, llo=0.f, lhi=0.f;
  float oacc[8][4];
  #pragma unroll
  for (int a=0;a<8;a++)
    #pragma unroll
    for (int b=0;b<4;b++) oacc[a][b]=0.f;

  // ---- cp.async tile loader: K,V row-major [128][72] ----
  auto load_tile = [&](int t0, int stg){
    __half* S = ds + stg*ASTAGE;
    for (int i=tid; i<1024; i+=256){
      int rr = i>>3, c = (i&7)*8;
      int so = rr*ASTR + c;
      size_t go = (size_t)(t0+rr)*HD + c;
      cpasync16(S        + so, kh + go);
      cpasync16(S + AARR + so, vh + go);
    }
    asm volatile("cp.async.commit_group;\n");
  };

  load_tile(0, 0);

  const int NT = SEQ/128;   // 16
  for (int t=0; t<NT; ++t){
    if (t+1 < NT){
      load_tile((t+1)*128, (t+1)&1);
      asm volatile("cp.async.wait_group 1;\n");
    } else {
      asm volatile("cp.async.wait_group 0;\n");
    }
    __syncthreads();

    const __half* Kt = ds + (t&1)*ASTAGE;
    const __half* Vt = Kt + AARR;

    #pragma unroll
    for (int sub=0; sub<2; ++sub){
      const __half* Kh = Kt + sub*64*ASTR;
      const __half* Vh = Vt + sub*64*ASTR;

      // ---- scores: S = Q K^T ----
      float sacc[8][4];
      #pragma unroll
      for (int a=0;a<8;a++)
        #pragma unroll
        for (int b=0;b<4;b++) sacc[a][b]=0.f;

      const int lg  = lane>>3;
      const int lri = lane&7;

      #pragma unroll
      for (int kk=0;kk<4;kk++){
        int ks = kk*16;
        #pragma unroll
        for (int nip=0; nip<8; nip+=2){
          int row = (nip + (lg>>1))*8 + lri;
          int col = ks + (lg&1)*8;
          uint32_t b0,b1,b2,b3;
          ldmx4(b0,b1,b2,b3, &Kh[row*ASTR + col]);
          mma16816(sacc[nip],   qfh[kk], b0, b1);
          mma16816(sacc[nip+1], qfh[kk], b2, b3);
        }
      }

      // ---- online softmax ----
      float rmax0=-1e30f, rmax1=-1e30f;
      #pragma unroll
      for (int ni=0;ni<8;ni++){
        #pragma unroll
        for (int j=0;j<4;j++) sacc[ni][j] *= 0.125f;   // 1/sqrt(64)
        rmax0 = fmaxf(rmax0, fmaxf(sacc[ni][0], sacc[ni][1]));
        rmax1 = fmaxf(rmax1, fmaxf(sacc[ni][2], sacc[ni][3]));
      }
      rmax0 = fmaxf(rmax0, __shfl_xor_sync(0xffffffffu, rmax0, 1));
      rmax0 = fmaxf(rmax0, __shfl_xor_sync(0xffffffffu, rmax0, 2));
      rmax1 = fmaxf(rmax1, __shfl_xor_sync(0xffffffffu, rmax1, 1));
      rmax1 = fmaxf(rmax1, __shfl_xor_sync(0xffffffffu, rmax1, 2));

      float mn0 = fmaxf(mlo, rmax0), mn1 = fmaxf(mhi, rmax1);
      float al0 = __expf(mlo-mn0), al1 = __expf(mhi-mn1);
      mlo = mn0; mhi = mn1;

      float sum0=0.f, sum1=0.f;
      uint32_t pf[8][2];
      #pragma unroll
      for (int ni=0;ni<8;ni++){
        float p0=__expf(sacc[ni][0]-mn0);
        float p1=__expf(sacc[ni][1]-mn0);
        float p2=__expf(sacc[ni][2]-mn1);
        float p3=__expf(sacc[ni][3]-mn1);
        sum0 += p0+p1; sum1 += p2+p3;
        __half2 h0=__floats2half2_rn(p0,p1);
        __half2 h1=__floats2half2_rn(p2,p3);
        pf[ni][0]=*reinterpret_cast<uint32_t*>(&h0);
        pf[ni][1]=*reinterpret_cast<uint32_t*>(&h1);
      }
      sum0 += __shfl_xor_sync(0xffffffffu,sum0,1);
      sum0 += __shfl_xor_sync(0xffffffffu,sum0,2);
      sum1 += __shfl_xor_sync(0xffffffffu,sum1,1);
      sum1 += __shfl_xor_sync(0xffffffffu,sum1,2);
      llo = llo*al0 + sum0;
      lhi = lhi*al1 + sum1;

      #pragma unroll
      for (int nd=0;nd<8;nd++){
        oacc[nd][0]*=al0; oacc[nd][1]*=al0;
        oacc[nd][2]*=al1; oacc[nd][3]*=al1;
      }

      // ---- PV: B-fragments of V^T via ldmatrix.x4.trans on row-major V ----
      #pragma unroll
      for (int kk=0;kk<4;kk++){
        uint32_t af[4] = {pf[2*kk][0], pf[2*kk][1], pf[2*kk+1][0], pf[2*kk+1][1]};
        int vrow = kk*16 + ((lane>>3)&1)*8 + (lane&7);
        #pragma unroll
        for (int nd=0;nd<8;nd+=2){
          int vcol = (nd + (lane>>4))*8;
          uint32_t b0,b1,b2,b3;
          ldmx4t(b0,b1,b2,b3, &Vh[vrow*ASTR + vcol]);
          mma16816(oacc[nd],   af, b0, b1);
          mma16816(oacc[nd+1], af, b2, b3);
        }
      }
    }
    __syncthreads();
  }

  float i0 = 1.f/llo, i1 = 1.f/lhi;
  int bb = bh >> 4, hh = bh & 15;
  #pragma unroll
  for (int nd=0;nd<8;nd++){
    int sr  = s0 + warp*16 + gi;
    int col = hh*HD + nd*8 + qd*2;
    size_t off = ((size_t)(bb*SEQ + sr))*DM + col;
    *reinterpret_cast<__half2*>(g_aoh+off) = __floats2half2_rn(oacc[nd][0]*i0, oacc[nd][1]*i0);
    size_t off2 = off + (size_t)8*DM;
    *reinterpret_cast<__half2*>(g_aoh+off2) = __floats2half2_rn(oacc[nd][2]*i1, oacc[nd][3]*i1);
  }
}

// -------- launcher --------
extern "C" void kernel_launch(void* const* d_in, const int* in_sizes, int n_in,
                              void* d_out, int out_size){
  (void)in_sizes; (void)n_in; (void)out_size;
  const float* x  = (const float*)d_in[0];
  const float* Wq = (const float*)d_in[1];
  const float* bq = (const float*)d_in[2];
  const float* Wk = (const float*)d_in[3];
  const float* bk = (const float*)d_in[4];
  const float* Wv = (const float*)d_in[5];
  const float* bv = (const float*)d_in[6];
  const float* Wo = (const float*)d_in[7];
  const float* bo = (const float*)d_in[8];
  const int*   rs = (const int*)d_in[9];
  float* out = (float*)d_out;

  cudaFuncSetAttribute(gemm_kernel, cudaFuncAttributeMaxDynamicSharedMemorySize, GSMEM_BYTES);
  cudaFuncSetAttribute(attn_kernel, cudaFuncAttributeMaxDynamicSharedMemorySize, ASMEM_BYTES);

  conv_x_kernel<<<(MTOT*DM)/(256*4), 256>>>(x);
  rope_tab_kernel<<<(SEQ*32)/256, 256>>>();
  conv_wt_kernel<<<dim3(32,32,4), dim3(32,8)>>>(Wq, Wk, Wv, Wo);

  // fused q/k/v projection: blockIdx.z = mode
  gemm_kernel<<<dim3(DM/128, MTOT/128, 3), 256, GSMEM_BYTES>>>(0, bq, bk, bv, rs, nullptr);

  attn_kernel<<<dim3(SEQ/128, BT*NH), 256, ASMEM_BYTES>>>();

  // output projection
  gemm_kernel<<<dim3(DM/128, MTOT/128, 1), 256, GSMEM_BYTES>>>(3, bo, bo, bo, rs, out);
}

// round 16
// speedup vs baseline: 1.1121x; 1.1121x over previous
#include <cuda_runtime.h>
#include <cuda_fp16.h>
#include <cstdint>

#define SEQ 2048
#define DM 1024
#define NH 16
#define HD 64
#define BT 4
#define MTOT (BT*SEQ)          // 8192
#define WSZ (DM*DM)

// gemm smem: 4 stages x (A 128x32 + B 64x32), stride 40 halfs
#define GSTR 40
#define GA_HALFS (128*GSTR)     // 5120
#define GB_HALFS (64*GSTR)      // 2560
#define GSTAGE (GA_HALFS+GB_HALFS) // 7680 halfs per stage
#define GNSTG 4
#define GSMEM_BYTES (GNSTG*GSTAGE*2)   // 61440 bytes

// attn smem (round-7 verified): 2 stages x 2 arrays (K,V) x 64 rows x 72 halfs
#define ASTR 72
#define AARR (64*ASTR)          // 4608 halfs
#define ASTAGE (2*AARR)         // 9216 halfs per stage
#define ASMEM_BYTES (2*ASTAGE*2)   // 36864 bytes

// -------- scratch (static device globals; allocation-free) --------
__device__ __align__(16) __half g_xh[MTOT*DM];
__device__ __align__(16) __half g_wth[4*WSZ];
__device__ __align__(16) __half g_qh[MTOT*DM];
__device__ __align__(16) __half g_kh[MTOT*DM];
__device__ __align__(16) __half g_vh[MTOT*DM];
__device__ __align__(16) __half g_aoh[MTOT*DM];
__device__ float g_ropec[SEQ*32];
__device__ float g_ropes[SEQ*32];

__device__ __forceinline__ void cpasync16(__half* s, const __half* g){
  uint32_t sa = (uint32_t)__cvta_generic_to_shared(s);
  asm volatile("cp.async.cg.shared.global [%0], [%1], 16;\n" :: "r"(sa), "l"(g));
}
__device__ __forceinline__ void ldmx4(uint32_t& r0, uint32_t& r1, uint32_t& r2, uint32_t& r3,
                                      const __half* p){
  uint32_t a = (uint32_t)__cvta_generic_to_shared(p);
  asm volatile("ldmatrix.sync.aligned.m8n8.x4.shared.b16 {%0,%1,%2,%3}, [%4];\n"
    : "=r"(r0), "=r"(r1), "=r"(r2), "=r"(r3) : "r"(a));
}
__device__ __forceinline__ void ldmx4t(uint32_t& r0, uint32_t& r1, uint32_t& r2, uint32_t& r3,
                                       const __half* p){
  uint32_t a = (uint32_t)__cvta_generic_to_shared(p);
  asm volatile("ldmatrix.sync.aligned.m8n8.x4.trans.shared.b16 {%0,%1,%2,%3}, [%4];\n"
    : "=r"(r0), "=r"(r1), "=r"(r2), "=r"(r3) : "r"(a));
}
__device__ __forceinline__ void mma16816(float* c, const uint32_t* a, uint32_t b0, uint32_t b1){
  asm volatile(
    "mma.sync.aligned.m16n8k16.row.col.f32.f16.f16.f32 "
    "{%0,%1,%2,%3}, {%4,%5,%6,%7}, {%8,%9}, {%0,%1,%2,%3};\n"
    : "+f"(c[0]), "+f"(c[1]), "+f"(c[2]), "+f"(c[3])
    : "r"(a[0]), "r"(a[1]), "r"(a[2]), "r"(a[3]), "r"(b0), "r"(b1));
}

// -------- conversion / table kernels --------
__global__ void conv_x_kernel(const float* __restrict__ x){
  int i = (blockIdx.x*blockDim.x + threadIdx.x)*4;
  float4 f = *reinterpret_cast<const float4*>(x + i);
  *reinterpret_cast<__half2*>(g_xh+i)   = __floats2half2_rn(f.x, f.y);
  *reinterpret_cast<__half2*>(g_xh+i+2) = __floats2half2_rn(f.z, f.w);
}

// rope table: cos/sin(pos * 10000^(-2j/64))
__global__ void rope_tab_kernel(){
  int i = blockIdx.x*blockDim.x + threadIdx.x;
  int p = i>>5, j = i&31;
  float fr = exp2f(-0.20762050593046013f * (float)(2*j));
  float sn, cs;
  sincosf((float)p*fr, &sn, &cs);
  g_ropec[i] = cs;
  g_ropes[i] = sn;
}

// transpose-convert: wt[n][k] = W[k][n].  blockIdx.z selects weight.
__global__ void conv_wt_kernel(const float* __restrict__ W0, const float* __restrict__ W1,
                               const float* __restrict__ W2, const float* __restrict__ W3){
  __shared__ float s[32][33];
  const int which = blockIdx.z;
  const float* W = (which==0)?W0:(which==1)?W1:(which==2)?W2:W3;
  int n0 = blockIdx.x*32, k0 = blockIdx.y*32;
  int tx = threadIdx.x, ty = threadIdx.y;
  #pragma unroll
  for (int i=0;i<32;i+=8) s[ty+i][tx] = W[(size_t)(k0+ty+i)*DM + n0+tx];
  __syncthreads();
  __half* dh = g_wth + (size_t)which*WSZ;
  #pragma unroll
  for (int i=0;i<32;i+=8)
    dh[(n0+ty+i)*DM + k0+tx] = __float2half_rn(s[tx][ty+i]);
}

// -------- fp16 GEMM: CTA tile 128x64, warp tile 32x32, 4-stage cp.async --------
// mode = mode_base + blockIdx.z: 0/1/2 = q/k/v (rope on 0,1), 3 = output projection
__global__ __launch_bounds__(256,3) void gemm_kernel(int mode_base,
                                                     const float* __restrict__ bias0,
                                                     const float* __restrict__ bias1,
                                                     const float* __restrict__ bias2,
                                                     const int* __restrict__ ropep,
                                                     float* __restrict__ outp){
  extern __shared__ __half ds[];

  const int mode = mode_base + blockIdx.z;
  const float* bias = (blockIdx.z==0)?bias0:(blockIdx.z==1)?bias1:bias2;

  const __half* Ah = (mode==3) ? g_aoh : g_xh;
  const __half* Bh = g_wth + (size_t)mode*WSZ;

  const int m0 = blockIdx.y*128;
  const int n0 = blockIdx.x*64;
  const int tid = threadIdx.x;
  const int warp = tid>>5, lane = tid&31;
  const int wm = warp&3, wn = warp>>2;        // 4 m-warps x 2 n-warps
  const int gi = lane>>2, qd = lane&3;
  const int lg = lane>>3, lri = lane&7;

  const __half* gA = Ah + (size_t)m0*DM;
  const __half* gB = Bh + (size_t)n0*DM;

  float acc[2][4][4];
  #pragma unroll
  for (int a=0;a<2;a++)
    #pragma unroll
    for (int b=0;b<4;b++)
      #pragma unroll
      for (int c=0;c<4;c++) acc[a][b][c]=0.f;

  // per-stage loader: A 512 chunks (2/thread), B 256 chunks (1/thread)
  const int ar0 = (tid>>2),       ac0 = (tid&3)*8;      // A chunk 0: rows 0..63
  const int ar1 = 64 + (tid>>2);                        // A chunk 1: rows 64..127
  const int br  = (tid>>2),       bc  = (tid&3)*8;

  auto load_chunk = [&](int kt, int s){
    __half* S = ds + s*GSTAGE;
    cpasync16(S + ar0*GSTR + ac0,            gA + (size_t)ar0*DM + kt + ac0);
    cpasync16(S + ar1*GSTR + ac0,            gA + (size_t)ar1*DM + kt + ac0);
    cpasync16(S + GA_HALFS + br*GSTR + bc,   gB + (size_t)br*DM  + kt + bc);
    asm volatile("cp.async.commit_group;\n");
  };

  const int NT = DM/32;   // 32
  load_chunk(0, 0);
  load_chunk(32, 1);
  load_chunk(64, 2);

  for (int t=0; t<NT; ++t){
    if (t <= NT-3)      asm volatile("cp.async.wait_group 2;\n");
    else if (t == NT-2) asm volatile("cp.async.wait_group 1;\n");
    else                asm volatile("cp.async.wait_group 0;\n");
    __syncthreads();
    if (t+3 < NT) load_chunk((t+3)*32, (t+3)&3);

    const __half* Ash = ds + (t&3)*GSTAGE;
    const __half* Bsh = Ash + GA_HALFS;

    #pragma unroll
    for (int ks=0; ks<32; ks+=16){
      uint32_t afh[2][4];
      const int arow = lane&15;
      const int acol = ks + (lane>>4)*8;
      #pragma unroll
      for (int mi=0;mi<2;mi++){
        int r = wm*32 + mi*16 + arow;
        ldmx4(afh[mi][0],afh[mi][1],afh[mi][2],afh[mi][3], &Ash[r*GSTR + acol]);
      }
      #pragma unroll
      for (int nip=0; nip<4; nip+=2){
        int row = wn*32 + (nip + (lg>>1))*8 + lri;
        int col = ks + (lg&1)*8;
        uint32_t b0,b1,b2,b3;
        ldmx4(b0,b1,b2,b3, &Bsh[row*GSTR + col]);
        #pragma unroll
        for (int mi=0;mi<2;mi++){
          mma16816(acc[mi][nip],   afh[mi], b0, b1);
          mma16816(acc[mi][nip+1], afh[mi], b2, b3);
        }
      }
    }
  }

  const int start = (mode<=1) ? *ropep : 0;
  #pragma unroll
  for (int mi=0;mi<2;mi++){
    #pragma unroll
    for (int ni=0;ni<4;ni++){
      int mrow = m0 + wm*32 + mi*16 + gi;
      int ncol = n0 + wn*32 + ni*8 + qd*2;
      float b0v = bias[ncol], b1v = bias[ncol+1];
      #pragma unroll
      for (int hf=0; hf<2; hf++){
        int mr = mrow + hf*8;
        float v0 = acc[mi][ni][hf*2+0] + b0v;
        float v1 = acc[mi][ni][hf*2+1] + b1v;
        if (mode==3){
          *reinterpret_cast<float2*>(outp + (size_t)mr*DM + ncol) = make_float2(v0,v1);
        } else {
          int bb = mr >> 11, ss = mr & 2047;
          int hh = ncol >> 6, dd = ncol & 63;
          if (mode<=1 && ss >= start){
            int pos = ss - start;
            int j   = (dd>>1);
            float cs = g_ropec[pos*32 + j];
            float sn = g_ropes[pos*32 + j];
            float e = v0*cs - v1*sn;
            float o = v1*cs + v0*sn;
            v0 = e; v1 = o;
          }
          int off = ((bb*NH + hh)*SEQ + ss)*HD + dd;
          __half* dh = (mode==0)?g_qh:(mode==1)?g_kh:g_vh;
          *reinterpret_cast<__half2*>(dh+off) = __floats2half2_rn(v0,v1);
        }
      }
    }
  }
}

// -------- flash attention (round-7 verified): 128-query tile, 8 warps, 64-row KV tiles --------
__global__ __launch_bounds__(256) void attn_kernel(){
  extern __shared__ __half ds[];

  const int bh = blockIdx.y;
  const int s0 = blockIdx.x*128;
  const int tid = threadIdx.x;
  const int warp = tid>>5, lane = tid&31;
  const int gi = lane>>2, qd = lane&3;

  const __half* qh = g_qh + (size_t)bh*SEQ*HD;
  const __half* kh = g_kh + (size_t)bh*SEQ*HD;
  const __half* vh = g_vh + (size_t)bh*SEQ*HD;

  {
    __half* Qh = ds;
    for (int idx=tid; idx<1024; idx+=256){
      int rr = idx>>3, c = (idx&7)*8;
      *reinterpret_cast<uint4*>(&Qh[rr*ASTR+c]) = *reinterpret_cast<const uint4*>(qh + (size_t)(s0+rr)*HD + c);
    }
  }
  __syncthreads();
  uint32_t qfh[4][4];
  {
    const __half* Qh = ds;
    const int arow = lane&15;
    #pragma unroll
    for (int kk=0;kk<4;kk++){
      int r = warp*16 + arow;
      int c = kk*16 + (lane>>4)*8;
      ldmx4(qfh[kk][0],qfh[kk][1],qfh[kk][2],qfh[kk][3], &Qh[r*ASTR + c]);
    }
  }
  __syncthreads();

  float mlo=-1e30f, mhi=-1e30f, llo=0.f, lhi=0.f;
  float oacc[8][4];
  #pragma unroll
  for (int a=0;a<8;a++)
    #pragma unroll
    for (int b=0;b<4;b++) oacc[a][b]=0.f;

  auto load_tile = [&](int t0, int stg){
    __half* S = ds + stg*ASTAGE;
    for (int i=tid; i<512; i+=256){
      int rr = i>>3, c = (i&7)*8;
      int so = rr*ASTR + c;
      size_t go = (size_t)(t0+rr)*HD + c;
      cpasync16(S        + so, kh + go);
      cpasync16(S + AARR + so, vh + go);
    }
    asm volatile("cp.async.commit_group;\n");
  };

  load_tile(0, 0);

  const int NT = SEQ/64;
  for (int t=0; t<NT; ++t){
    if (t+1 < NT){
      load_tile((t+1)*64, (t+1)&1);
      asm volatile("cp.async.wait_group 1;\n");
    } else {
      asm volatile("cp.async.wait_group 0;\n");
    }
    __syncthreads();

    const __half* Kh = ds + (t&1)*ASTAGE;
    const __half* Vh = Kh + AARR;

    float sacc[8][4];
    #pragma unroll
    for (int a=0;a<8;a++)
      #pragma unroll
      for (int b=0;b<4;b++) sacc[a][b]=0.f;

    const int lg  = lane>>3;
    const int lri = lane&7;

    #pragma unroll
    for (int kk=0;kk<4;kk++){
      int ks = kk*16;
      #pragma unroll
      for (int nip=0; nip<8; nip+=2){
        int row = (nip + (lg>>1))*8 + lri;
        int col = ks + (lg&1)*8;
        uint32_t b0,b1,b2,b3;
        ldmx4(b0,b1,b2,b3, &Kh[row*ASTR + col]);
        mma16816(sacc[nip],   qfh[kk], b0, b1);
        mma16816(sacc[nip+1], qfh[kk], b2, b3);
      }
    }

    float rmax0=-1e30f, rmax1=-1e30f;
    #pragma unroll
    for (int ni=0;ni<8;ni++){
      #pragma unroll
      for (int j=0;j<4;j++) sacc[ni][j] *= 0.125f;
      rmax0 = fmaxf(rmax0, fmaxf(sacc[ni][0], sacc[ni][1]));
      rmax1 = fmaxf(rmax1, fmaxf(sacc[ni][2], sacc[ni][3]));
    }
    rmax0 = fmaxf(rmax0, __shfl_xor_sync(0xffffffffu, rmax0, 1));
    rmax0 = fmaxf(rmax0, __shfl_xor_sync(0xffffffffu, rmax0, 2));
    rmax1 = fmaxf(rmax1, __shfl_xor_sync(0xffffffffu, rmax1, 1));
    rmax1 = fmaxf(rmax1, __shfl_xor_sync(0xffffffffu, rmax1, 2));

    float mn0 = fmaxf(mlo, rmax0), mn1 = fmaxf(mhi, rmax1);
    float al0 = __expf(mlo-mn0), al1 = __expf(mhi-mn1);
    mlo = mn0; mhi = mn1;

    float sum0=0.f, sum1=0.f;
    uint32_t pf[8][2];
    #pragma unroll
    for (int ni=0;ni<8;ni++){
      float p0=__expf(sacc[ni][0]-mn0);
      float p1=__expf(sacc[ni][1]-mn0);
      float p2=__expf(sacc[ni][2]-mn1);
      float p3=__expf(sacc[ni][3]-mn1);
      sum0 += p0+p1; sum1 += p2+p3;
      __half2 h0=__floats2half2_rn(p0,p1);
      __half2 h1=__floats2half2_rn(p2,p3);
      pf[ni][0]=*reinterpret_cast<uint32_t*>(&h0);
      pf[ni][1]=*reinterpret_cast<uint32_t*>(&h1);
    }
    sum0 += __shfl_xor_sync(0xffffffffu,sum0,1);
    sum0 += __shfl_xor_sync(0xffffffffu,sum0,2);
    sum1 += __shfl_xor_sync(0xffffffffu,sum1,1);
    sum1 += __shfl_xor_sync(0xffffffffu,sum1,2);
    llo = llo*al0 + sum0;
    lhi = lhi*al1 + sum1;

    #pragma unroll
    for (int nd=0;nd<8;nd++){
      oacc[nd][0]*=al0; oacc[nd][1]*=al0;
      oacc[nd][2]*=al1; oacc[nd][3]*=al1;
    }

    #pragma unroll
    for (int kk=0;kk<4;kk++){
      uint32_t af[4] = {pf[2*kk][0], pf[2*kk][1], pf[2*kk+1][0], pf[2*kk+1][1]};
      int vrow = kk*16 + ((lane>>3)&1)*8 + (lane&7);
      #pragma unroll
      for (int nd=0;nd<8;nd+=2){
        int vcol = (nd + (lane>>4))*8;
        uint32_t b0,b1,b2,b3;
        ldmx4t(b0,b1,b2,b3, &Vh[vrow*ASTR + vcol]);
        mma16816(oacc[nd],   af, b0, b1);
        mma16816(oacc[nd+1], af, b2, b3);
      }
    }
    __syncthreads();
  }

  float i0 = 1.f/llo, i1 = 1.f/lhi;
  int bb = bh >> 4, hh = bh & 15;
  #pragma unroll
  for (int nd=0;nd<8;nd++){
    int sr  = s0 + warp*16 + gi;
    int col = hh*HD + nd*8 + qd*2;
    size_t off = ((size_t)(bb*SEQ + sr))*DM + col;
    *reinterpret_cast<__half2*>(g_aoh+off) = __floats2half2_rn(oacc[nd][0]*i0, oacc[nd][1]*i0);
    size_t off2 = off + (size_t)8*DM;
    *reinterpret_cast<__half2*>(g_aoh+off2) = __floats2half2_rn(oacc[nd][2]*i1, oacc[nd][3]*i1);
  }
}

// -------- launcher --------
extern "C" void kernel_launch(void* const* d_in, const int* in_sizes, int n_in,
                              void* d_out, int out_size){
  (void)in_sizes; (void)n_in; (void)out_size;
  const float* x  = (const float*)d_in[0];
  const float* Wq = (const float*)d_in[1];
  const float* bq = (const float*)d_in[2];
  const float* Wk = (const float*)d_in[3];
  const float* bk = (const float*)d_in[4];
  const float* Wv = (const float*)d_in[5];
  const float* bv = (const float*)d_in[6];
  const float* Wo = (const float*)d_in[7];
  const float* bo = (const float*)d_in[8];
  const int*   rs = (const int*)d_in[9];
  float* out = (float*)d_out;

  cudaFuncSetAttribute(gemm_kernel, cudaFuncAttributeMaxDynamicSharedMemorySize, GSMEM_BYTES);
  cudaFuncSetAttribute(attn_kernel, cudaFuncAttributeMaxDynamicSharedMemorySize, ASMEM_BYTES);

  conv_x_kernel<<<(MTOT*DM)/(256*4), 256>>>(x);
  rope_tab_kernel<<<(SEQ*32)/256, 256>>>();
  conv_wt_kernel<<<dim3(32,32,4), dim3(32,8)>>>(Wq, Wk, Wv, Wo);

  // fused q/k/v projection: blockIdx.z = mode  (N-tile 64 -> grid.x 16)
  gemm_kernel<<<dim3(DM/64, MTOT/128, 3), 256, GSMEM_BYTES>>>(0, bq, bk, bv, rs, nullptr);

  attn_kernel<<<dim3(SEQ/128, BT*NH), 256, ASMEM_BYTES>>>();

  // output projection
  gemm_kernel<<<dim3(DM/64, MTOT/128, 1), 256, GSMEM_BYTES>>>(3, bo, bo, bo, rs, out);
}

// round 17
// speedup vs baseline: 1.1380x; 1.0234x over previous
#include <cuda_runtime.h>
#include <cuda_fp16.h>
#include <cstdint>

#define SEQ 2048
#define DM 1024
#define NH 16
#define HD 64
#define BT 4
#define MTOT (BT*SEQ)          // 8192
#define WSZ (DM*DM)

// gemm smem: 4 stages x (A 128x32 + B 128x32), stride 40 halfs
#define GSTR 40
#define GA_HALFS (128*GSTR)     // 5120
#define GB_HALFS (128*GSTR)     // 5120
#define GSTAGE (GA_HALFS+GB_HALFS) // 10240 halfs per stage
#define GNSTG 4
#define GSMEM_BYTES (GNSTG*GSTAGE*2)   // 81920 bytes

// attn smem (verified): 2 stages x 2 arrays (K,V) x 64 rows x 72 halfs
#define ASTR 72
#define AARR (64*ASTR)          // 4608 halfs
#define ASTAGE (2*AARR)         // 9216 halfs per stage
#define ASMEM_BYTES (2*ASTAGE*2)   // 36864 bytes

// -------- scratch (static device globals; allocation-free) --------
__device__ __align__(16) __half g_xh[MTOT*DM];
__device__ __align__(16) __half g_wth[4*WSZ];
__device__ __align__(16) __half g_qh[MTOT*DM];
__device__ __align__(16) __half g_kh[MTOT*DM];
__device__ __align__(16) __half g_vh[MTOT*DM];
__device__ __align__(16) __half g_aoh[MTOT*DM];
__device__ float g_ropec[SEQ*32];
__device__ float g_ropes[SEQ*32];

__device__ __forceinline__ void cpasync16(__half* s, const __half* g){
  uint32_t sa = (uint32_t)__cvta_generic_to_shared(s);
  asm volatile("cp.async.cg.shared.global [%0], [%1], 16;\n" :: "r"(sa), "l"(g));
}
__device__ __forceinline__ void ldmx4(uint32_t& r0, uint32_t& r1, uint32_t& r2, uint32_t& r3,
                                      const __half* p){
  uint32_t a = (uint32_t)__cvta_generic_to_shared(p);
  asm volatile("ldmatrix.sync.aligned.m8n8.x4.shared.b16 {%0,%1,%2,%3}, [%4];\n"
    : "=r"(r0), "=r"(r1), "=r"(r2), "=r"(r3) : "r"(a));
}
__device__ __forceinline__ void ldmx4t(uint32_t& r0, uint32_t& r1, uint32_t& r2, uint32_t& r3,
                                       const __half* p){
  uint32_t a = (uint32_t)__cvta_generic_to_shared(p);
  asm volatile("ldmatrix.sync.aligned.m8n8.x4.trans.shared.b16 {%0,%1,%2,%3}, [%4];\n"
    : "=r"(r0), "=r"(r1), "=r"(r2), "=r"(r3) : "r"(a));
}
__device__ __forceinline__ void mma16816(float* c, const uint32_t* a, uint32_t b0, uint32_t b1){
  asm volatile(
    "mma.sync.aligned.m16n8k16.row.col.f32.f16.f16.f32 "
    "{%0,%1,%2,%3}, {%4,%5,%6,%7}, {%8,%9}, {%0,%1,%2,%3};\n"
    : "+f"(c[0]), "+f"(c[1]), "+f"(c[2]), "+f"(c[3])
    : "r"(a[0]), "r"(a[1]), "r"(a[2]), "r"(a[3]), "r"(b0), "r"(b1));
}

// -------- conversion / table kernels --------
__global__ void conv_x_kernel(const float* __restrict__ x){
  int i = (blockIdx.x*blockDim.x + threadIdx.x)*4;
  float4 f = *reinterpret_cast<const float4*>(x + i);
  *reinterpret_cast<__half2*>(g_xh+i)   = __floats2half2_rn(f.x, f.y);
  *reinterpret_cast<__half2*>(g_xh+i+2) = __floats2half2_rn(f.z, f.w);
}

// rope table: cos/sin(pos * 10000^(-2j/64))
__global__ void rope_tab_kernel(){
  int i = blockIdx.x*blockDim.x + threadIdx.x;
  int p = i>>5, j = i&31;
  float fr = exp2f(-0.20762050593046013f * (float)(2*j));
  float sn, cs;
  sincosf((float)p*fr, &sn, &cs);
  g_ropec[i] = cs;
  g_ropes[i] = sn;
}

// transpose-convert: wt[n][k] = W[k][n].  blockIdx.z selects weight.
__global__ void conv_wt_kernel(const float* __restrict__ W0, const float* __restrict__ W1,
                               const float* __restrict__ W2, const float* __restrict__ W3){
  __shared__ float s[32][33];
  const int which = blockIdx.z;
  const float* W = (which==0)?W0:(which==1)?W1:(which==2)?W2:W3;
  int n0 = blockIdx.x*32, k0 = blockIdx.y*32;
  int tx = threadIdx.x, ty = threadIdx.y;
  #pragma unroll
  for (int i=0;i<32;i+=8) s[ty+i][tx] = W[(size_t)(k0+ty+i)*DM + n0+tx];
  __syncthreads();
  __half* dh = g_wth + (size_t)which*WSZ;
  #pragma unroll
  for (int i=0;i<32;i+=8)
    dh[(n0+ty+i)*DM + k0+tx] = __float2half_rn(s[tx][ty+i]);
}

// -------- fp16 GEMM: CTA tile 128x128, warp tile 32x64 (4m x 2n), 4-stage cp.async,
// single barrier per iteration --------
// mode = mode_base + blockIdx.z: 0/1/2 = q/k/v (rope on 0,1), 3 = output projection
__global__ __launch_bounds__(256,2) void gemm_kernel(int mode_base,
                                                     const float* __restrict__ bias0,
                                                     const float* __restrict__ bias1,
                                                     const float* __restrict__ bias2,
                                                     const int* __restrict__ ropep,
                                                     float* __restrict__ outp){
  extern __shared__ __half ds[];

  const int mode = mode_base + blockIdx.z;
  const float* bias = (blockIdx.z==0)?bias0:(blockIdx.z==1)?bias1:bias2;

  const __half* Ah = (mode==3) ? g_aoh : g_xh;
  const __half* Bh = g_wth + (size_t)mode*WSZ;

  const int m0 = blockIdx.y*128;
  const int n0 = blockIdx.x*128;
  const int tid = threadIdx.x;
  const int warp = tid>>5, lane = tid&31;
  const int wm = warp&3, wn = warp>>2;        // 4 m-warps x 2 n-warps
  const int gi = lane>>2, qd = lane&3;
  const int lg = lane>>3, lri = lane&7;

  const __half* gA = Ah + (size_t)m0*DM;
  const __half* gB = Bh + (size_t)n0*DM;

  float acc[2][8][4];
  #pragma unroll
  for (int a=0;a<2;a++)
    #pragma unroll
    for (int b=0;b<8;b++)
      #pragma unroll
      for (int c=0;c<4;c++) acc[a][b][c]=0.f;

  // per-stage loader: A 512 chunks (2/thread), B 512 chunks (2/thread)
  const int r0 = (tid>>2),        c0 = (tid&3)*8;      // rows 0..63
  const int r1 = 64 + (tid>>2);                        // rows 64..127

  auto load_chunk = [&](int kt, int s){
    __half* S = ds + s*GSTAGE;
    cpasync16(S + r0*GSTR + c0,             gA + (size_t)r0*DM + kt + c0);
    cpasync16(S + r1*GSTR + c0,             gA + (size_t)r1*DM + kt + c0);
    cpasync16(S + GA_HALFS + r0*GSTR + c0,  gB + (size_t)r0*DM + kt + c0);
    cpasync16(S + GA_HALFS + r1*GSTR + c0,  gB + (size_t)r1*DM + kt + c0);
    asm volatile("cp.async.commit_group;\n");
  };

  const int NT = DM/32;   // 32
  load_chunk(0, 0);
  load_chunk(32, 1);
  load_chunk(64, 2);

  for (int t=0; t<NT; ++t){
    if (t <= NT-3)      asm volatile("cp.async.wait_group 2;\n");
    else if (t == NT-2) asm volatile("cp.async.wait_group 1;\n");
    else                asm volatile("cp.async.wait_group 0;\n");
    __syncthreads();
    if (t+3 < NT) load_chunk((t+3)*32, (t+3)&3);

    const __half* Ash = ds + (t&3)*GSTAGE;
    const __half* Bsh = Ash + GA_HALFS;

    #pragma unroll
    for (int ks=0; ks<32; ks+=16){
      uint32_t afh[2][4];
      const int arow = lane&15;
      const int acol = ks + (lane>>4)*8;
      #pragma unroll
      for (int mi=0;mi<2;mi++){
        int r = wm*32 + mi*16 + arow;
        ldmx4(afh[mi][0],afh[mi][1],afh[mi][2],afh[mi][3], &Ash[r*GSTR + acol]);
      }
      #pragma unroll
      for (int nip=0; nip<8; nip+=2){
        int row = wn*64 + (nip + (lg>>1))*8 + lri;
        int col = ks + (lg&1)*8;
        uint32_t b0,b1,b2,b3;
        ldmx4(b0,b1,b2,b3, &Bsh[row*GSTR + col]);
        #pragma unroll
        for (int mi=0;mi<2;mi++){
          mma16816(acc[mi][nip],   afh[mi], b0, b1);
          mma16816(acc[mi][nip+1], afh[mi], b2, b3);
        }
      }
    }
  }

  const int start = (mode<=1) ? *ropep : 0;
  #pragma unroll
  for (int mi=0;mi<2;mi++){
    #pragma unroll
    for (int ni=0;ni<8;ni++){
      int mrow = m0 + wm*32 + mi*16 + gi;
      int ncol = n0 + wn*64 + ni*8 + qd*2;
      float b0v = bias[ncol], b1v = bias[ncol+1];
      #pragma unroll
      for (int hf=0; hf<2; hf++){
        int mr = mrow + hf*8;
        float v0 = acc[mi][ni][hf*2+0] + b0v;
        float v1 = acc[mi][ni][hf*2+1] + b1v;
        if (mode==3){
          *reinterpret_cast<float2*>(outp + (size_t)mr*DM + ncol) = make_float2(v0,v1);
        } else {
          int bb = mr >> 11, ss = mr & 2047;
          int hh = ncol >> 6, dd = ncol & 63;
          if (mode<=1 && ss >= start){
            int pos = ss - start;
            int j   = (dd>>1);
            float cs = g_ropec[pos*32 + j];
            float sn = g_ropes[pos*32 + j];
            float e = v0*cs - v1*sn;
            float o = v1*cs + v0*sn;
            v0 = e; v1 = o;
          }
          int off = ((bb*NH + hh)*SEQ + ss)*HD + dd;
          __half* dh = (mode==0)?g_qh:(mode==1)?g_kh:g_vh;
          *reinterpret_cast<__half2*>(dh+off) = __floats2half2_rn(v0,v1);
        }
      }
    }
  }
}

// -------- flash attention (verified): 128-query tile, 8 warps, 64-row KV tiles --------
__global__ __launch_bounds__(256) void attn_kernel(){
  extern __shared__ __half ds[];

  const int bh = blockIdx.y;
  const int s0 = blockIdx.x*128;
  const int tid = threadIdx.x;
  const int warp = tid>>5, lane = tid&31;
  const int gi = lane>>2, qd = lane&3;

  const __half* qh = g_qh + (size_t)bh*SEQ*HD;
  const __half* kh = g_kh + (size_t)bh*SEQ*HD;
  const __half* vh = g_vh + (size_t)bh*SEQ*HD;

  {
    __half* Qh = ds;
    for (int idx=tid; idx<1024; idx+=256){
      int rr = idx>>3, c = (idx&7)*8;
      *reinterpret_cast<uint4*>(&Qh[rr*ASTR+c]) = *reinterpret_cast<const uint4*>(qh + (size_t)(s0+rr)*HD + c);
    }
  }
  __syncthreads();
  uint32_t qfh[4][4];
  {
    const __half* Qh = ds;
    const int arow = lane&15;
    #pragma unroll
    for (int kk=0;kk<4;kk++){
      int r = warp*16 + arow;
      int c = kk*16 + (lane>>4)*8;
      ldmx4(qfh[kk][0],qfh[kk][1],qfh[kk][2],qfh[kk][3], &Qh[r*ASTR + c]);
    }
  }
  __syncthreads();

  float mlo=-1e30f, mhi=-1e30f, llo=0.f, lhi=0.f;
  float oacc[8][4];
  #pragma unroll
  for (int a=0;a<8;a++)
    #pragma unroll
    for (int b=0;b<4;b++) oacc[a][b]=0.f;

  auto load_tile = [&](int t0, int stg){
    __half* S = ds + stg*ASTAGE;
    for (int i=tid; i<512; i+=256){
      int rr = i>>3, c = (i&7)*8;
      int so = rr*ASTR + c;
      size_t go = (size_t)(t0+rr)*HD + c;
      cpasync16(S        + so, kh + go);
      cpasync16(S + AARR + so, vh + go);
    }
    asm volatile("cp.async.commit_group;\n");
  };

  load_tile(0, 0);

  const int NT = SEQ/64;
  for (int t=0; t<NT; ++t){
    if (t+1 < NT){
      load_tile((t+1)*64, (t+1)&1);
      asm volatile("cp.async.wait_group 1;\n");
    } else {
      asm volatile("cp.async.wait_group 0;\n");
    }
    __syncthreads();

    const __half* Kh = ds + (t&1)*ASTAGE;
    const __half* Vh = Kh + AARR;

    float sacc[8][4];
    #pragma unroll
    for (int a=0;a<8;a++)
      #pragma unroll
      for (int b=0;b<4;b++) sacc[a][b]=0.f;

    const int lg  = lane>>3;
    const int lri = lane&7;

    #pragma unroll
    for (int kk=0;kk<4;kk++){
      int ks = kk*16;
      #pragma unroll
      for (int nip=0; nip<8; nip+=2){
        int row = (nip + (lg>>1))*8 + lri;
        int col = ks + (lg&1)*8;
        uint32_t b0,b1,b2,b3;
        ldmx4(b0,b1,b2,b3, &Kh[row*ASTR + col]);
        mma16816(sacc[nip],   qfh[kk], b0, b1);
        mma16816(sacc[nip+1], qfh[kk], b2, b3);
      }
    }

    float rmax0=-1e30f, rmax1=-1e30f;
    #pragma unroll
    for (int ni=0;ni<8;ni++){
      #pragma unroll
      for (int j=0;j<4;j++) sacc[ni][j] *= 0.125f;
      rmax0 = fmaxf(rmax0, fmaxf(sacc[ni][0], sacc[ni][1]));
      rmax1 = fmaxf(rmax1, fmaxf(sacc[ni][2], sacc[ni][3]));
    }
    rmax0 = fmaxf(rmax0, __shfl_xor_sync(0xffffffffu, rmax0, 1));
    rmax0 = fmaxf(rmax0, __shfl_xor_sync(0xffffffffu, rmax0, 2));
    rmax1 = fmaxf(rmax1, __shfl_xor_sync(0xffffffffu, rmax1, 1));
    rmax1 = fmaxf(rmax1, __shfl_xor_sync(0xffffffffu, rmax1, 2));

    float mn0 = fmaxf(mlo, rmax0), mn1 = fmaxf(mhi, rmax1);
    float al0 = __expf(mlo-mn0), al1 = __expf(mhi-mn1);
    mlo = mn0; mhi = mn1;

    float sum0=0.f, sum1=0.f;
    uint32_t pf[8][2];
    #pragma unroll
    for (int ni=0;ni<8;ni++){
      float p0=__expf(sacc[ni][0]-mn0);
      float p1=__expf(sacc[ni][1]-mn0);
      float p2=__expf(sacc[ni][2]-mn1);
      float p3=__expf(sacc[ni][3]-mn1);
      sum0 += p0+p1; sum1 += p2+p3;
      __half2 h0=__floats2half2_rn(p0,p1);
      __half2 h1=__floats2half2_rn(p2,p3);
      pf[ni][0]=*reinterpret_cast<uint32_t*>(&h0);
      pf[ni][1]=*reinterpret_cast<uint32_t*>(&h1);
    }
    sum0 += __shfl_xor_sync(0xffffffffu,sum0,1);
    sum0 += __shfl_xor_sync(0xffffffffu,sum0,2);
    sum1 += __shfl_xor_sync(0xffffffffu,sum1,1);
    sum1 += __shfl_xor_sync(0xffffffffu,sum1,2);
    llo = llo*al0 + sum0;
    lhi = lhi*al1 + sum1;

    #pragma unroll
    for (int nd=0;nd<8;nd++){
      oacc[nd][0]*=al0; oacc[nd][1]*=al0;
      oacc[nd][2]*=al1; oacc[nd][3]*=al1;
    }

    #pragma unroll
    for (int kk=0;kk<4;kk++){
      uint32_t af[4] = {pf[2*kk][0], pf[2*kk][1], pf[2*kk+1][0], pf[2*kk+1][1]};
      int vrow = kk*16 + ((lane>>3)&1)*8 + (lane&7);
      #pragma unroll
      for (int nd=0;nd<8;nd+=2){
        int vcol = (nd + (lane>>4))*8;
        uint32_t b0,b1,b2,b3;
        ldmx4t(b0,b1,b2,b3, &Vh[vrow*ASTR + vcol]);
        mma16816(oacc[nd],   af, b0, b1);
        mma16816(oacc[nd+1], af, b2, b3);
      }
    }
    __syncthreads();
  }

  float i0 = 1.f/llo, i1 = 1.f/lhi;
  int bb = bh >> 4, hh = bh & 15;
  #pragma unroll
  for (int nd=0;nd<8;nd++){
    int sr  = s0 + warp*16 + gi;
    int col = hh*HD + nd*8 + qd*2;
    size_t off = ((size_t)(bb*SEQ + sr))*DM + col;
    *reinterpret_cast<__half2*>(g_aoh+off) = __floats2half2_rn(oacc[nd][0]*i0, oacc[nd][1]*i0);
    size_t off2 = off + (size_t)8*DM;
    *reinterpret_cast<__half2*>(g_aoh+off2) = __floats2half2_rn(oacc[nd][2]*i1, oacc[nd][3]*i1);
  }
}

// -------- launcher --------
extern "C" void kernel_launch(void* const* d_in, const int* in_sizes, int n_in,
                              void* d_out, int out_size){
  (void)in_sizes; (void)n_in; (void)out_size;
  const float* x  = (const float*)d_in[0];
  const float* Wq = (const float*)d_in[1];
  const float* bq = (const float*)d_in[2];
  const float* Wk = (const float*)d_in[3];
  const float* bk = (const float*)d_in[4];
  const float* Wv = (const float*)d_in[5];
  const float* bv = (const float*)d_in[6];
  const float* Wo = (const float*)d_in[7];
  const float* bo = (const float*)d_in[8];
  const int*   rs = (const int*)d_in[9];
  float* out = (float*)d_out;

  cudaFuncSetAttribute(gemm_kernel, cudaFuncAttributeMaxDynamicSharedMemorySize, GSMEM_BYTES);
  cudaFuncSetAttribute(attn_kernel, cudaFuncAttributeMaxDynamicSharedMemorySize, ASMEM_BYTES);

  conv_x_kernel<<<(MTOT*DM)/(256*4), 256>>>(x);
  rope_tab_kernel<<<(SEQ*32)/256, 256>>>();
  conv_wt_kernel<<<dim3(32,32,4), dim3(32,8)>>>(Wq, Wk, Wv, Wo);

  // fused q/k/v projection: blockIdx.z = mode  (N-tile 128 -> grid.x 8)
  gemm_kernel<<<dim3(DM/128, MTOT/128, 3), 256, GSMEM_BYTES>>>(0, bq, bk, bv, rs, nullptr);

  attn_kernel<<<dim3(SEQ/128, BT*NH), 256, ASMEM_BYTES>>>();

  // output projection
  gemm_kernel<<<dim3(DM/128, MTOT/128, 1), 256, GSMEM_BYTES>>>(3, bo, bo, bo, rs, out);
}